// round 16
// baseline (speedup 1.0000x reference)
#include <cuda_runtime.h>
#include <cuda_fp16.h>
#include <math.h>
#include <stdint.h>

#define NN 50000
#define NE 800000
#define HD 256
#define MPAD 50048            // 391 * 128
#define STAGE_BYTES 32768     // A 16KB + B 16KB per stage
#define SMEM_TOTAL (2 * STAGE_BYTES)
#define NBLK 196              // scan blocks (196*256 = 50176 >= NN)
#define GEMM_BLOCKS 782       // 391 m-tiles * 2 n-tiles
#define AGG_BLOCKS 6250       // 6250 * 8 warps = 50000 nodes
#define K1_GRID 7032          // interleaved 1 gemm : 8 agg

// ---- device scratch (fp16 features + fp16 weights) ----
__device__ __align__(16) unsigned short g_AG[(size_t)MPAD * HD];
__device__ __align__(16) unsigned short g_X0[(size_t)MPAD * HD];
__device__ __align__(16) unsigned short g_X1[(size_t)MPAD * HD];
__device__ __align__(16) float          g_P[(size_t)MPAD * HD];   // fp32 partial X*Wr
// weights: [layer][n][k] with k = [Wl 0..255 | Wr 256..511]
__device__ __align__(16) unsigned short g_B[3 * 256 * 512];
__device__ int   g_rowptr[NN + 1];
__device__ int   g_col[NE];
__device__ int   g_src[NE];
__device__ int   g_dst[NE];
__device__ int   g_cnt[NN];
__device__ int   g_wpos[NN];
__device__ int   g_part[NBLK];
__device__ float g_invdeg[NN];
__device__ int   g_is32;

// ---- helpers ----
__device__ __forceinline__ unsigned short f2h(float v) {
    return __half_as_ushort(__float2half_rn(v));
}
__device__ __forceinline__ uint32_t smem_u32(const void* p) {
    uint32_t a;
    asm("{ .reg .u64 t; cvta.to.shared.u64 t, %1; cvt.u32.u64 %0, t; }" : "=r"(a) : "l"(p));
    return a;
}
#define SW128(o) ((o) ^ (((o) >> 3) & 0x70))

#define CP16(sm, gp) asm volatile("cp.async.cg.shared.global [%0], [%1], 16;" :: "r"(sm), "l"(gp) : "memory")
#define CP_COMMIT()  asm volatile("cp.async.commit_group;" ::: "memory")
#define CP_WAIT(n)   asm volatile("cp.async.wait_group %0;" :: "n"(n) : "memory")

__device__ __forceinline__ void ldsm4(uint32_t* r, uint32_t addr) {
    asm volatile("ldmatrix.sync.aligned.m8n8.x4.shared.b16 {%0,%1,%2,%3}, [%4];"
        : "=r"(r[0]), "=r"(r[1]), "=r"(r[2]), "=r"(r[3]) : "r"(addr));
}
__device__ __forceinline__ void mma16816(float* c, const uint32_t* a, const uint32_t* b) {
    asm volatile("mma.sync.aligned.m16n8k16.row.col.f32.f16.f16.f32 "
        "{%0,%1,%2,%3}, {%4,%5,%6,%7}, {%8,%9}, {%0,%1,%2,%3};"
        : "+f"(c[0]), "+f"(c[1]), "+f"(c[2]), "+f"(c[3])
        : "r"(a[0]), "r"(a[1]), "r"(a[2]), "r"(a[3]), "r"(b[0]), "r"(b[1]));
}

// ---------------- edge dtype probe (+ zero fused) ----------------
__global__ void k_zero_detect(const int* __restrict__ e32) {
    int i = blockIdx.x * blockDim.x + threadIdx.x;
    if (i == 0) g_is32 = 0;
    if (i < NN) { g_cnt[i] = 0; g_wpos[i] = 0; }
}

__global__ void k_detect(const int* __restrict__ e32) {
    int i = blockIdx.x * blockDim.x + threadIdx.x;
    if (i < 4096) {
        if (e32[2 * i + 1] != 0) atomicOr(&g_is32, 1);
    }
}

// convert + degree count fused
__global__ void k_convert_count(const int* __restrict__ e32) {
    int i = blockIdx.x * blockDim.x + threadIdx.x;
    if (i >= NE) return;
    int s, d;
    if (g_is32) { s = e32[i]; d = e32[NE + i]; }
    else        { s = e32[2 * i]; d = e32[2 * (NE + i)]; }
    if (s < 0) s = 0; if (s >= NN) s = NN - 1;
    if (d < 0) d = 0; if (d >= NN) d = NN - 1;
    g_src[i] = s;
    g_dst[i] = d;
    atomicAdd(&g_cnt[d], 1);
}

// ---------------- parallel 3-phase scan ----------------
__global__ void k_blocksum() {
    __shared__ int sh[256];
    int i = blockIdx.x * 256 + threadIdx.x;
    int v = (i < NN) ? g_cnt[i] : 0;
    sh[threadIdx.x] = v;
    __syncthreads();
#pragma unroll
    for (int off = 128; off > 0; off >>= 1) {
        if (threadIdx.x < off) sh[threadIdx.x] += sh[threadIdx.x + off];
        __syncthreads();
    }
    if (threadIdx.x == 0) g_part[blockIdx.x] = sh[0];
}

__global__ void k_scanpart() {
    __shared__ int sh[256];
    int tid = threadIdx.x;
    int v = (tid < NBLK) ? g_part[tid] : 0;
    sh[tid] = v;
    __syncthreads();
#pragma unroll
    for (int off = 1; off < 256; off <<= 1) {
        int u = (tid >= off) ? sh[tid - off] : 0;
        __syncthreads();
        sh[tid] += u;
        __syncthreads();
    }
    if (tid < NBLK) g_part[tid] = sh[tid] - v;   // exclusive
    if (tid == 255) g_rowptr[NN] = sh[255];
}

__global__ void k_rowptr() {
    __shared__ int sh[256];
    int tid = threadIdx.x;
    int i = blockIdx.x * 256 + tid;
    int v = (i < NN) ? g_cnt[i] : 0;
    sh[tid] = v;
    __syncthreads();
#pragma unroll
    for (int off = 1; off < 256; off <<= 1) {
        int u = (tid >= off) ? sh[tid - off] : 0;
        __syncthreads();
        sh[tid] += u;
        __syncthreads();
    }
    if (i < NN) {
        g_rowptr[i] = g_part[blockIdx.x] + sh[tid] - v;   // exclusive
        g_invdeg[i] = 1.0f / (float)(v > 1 ? v : 1);
    }
}

__global__ void k_fill() {
    int e = blockIdx.x * blockDim.x + threadIdx.x;
    if (e < NE) {
        int d = g_dst[e];
        int p = atomicAdd(&g_wpos[d], 1);
        g_col[g_rowptr[d] + p] = g_src[e];
    }
}

// ---------------- weight / x conversion ----------------
__global__ void k_wconv(const float* __restrict__ W0, const float* __restrict__ W1,
                        const float* __restrict__ W2, const float* __restrict__ W3,
                        const float* __restrict__ W4, const float* __restrict__ W5) {
    int i = blockIdx.x * blockDim.x + threadIdx.x;
    if (i >= 3 * 256 * 512) return;
    int layer = i / (256 * 512);
    int r = i % (256 * 512);
    int n = r / 512, k = r % 512;
    const float* Wl = (layer == 0) ? W0 : ((layer == 1) ? W2 : W4);
    const float* Wr = (layer == 0) ? W1 : ((layer == 1) ? W3 : W5);
    float v = (k < 256) ? Wl[n * 256 + k] : Wr[n * 256 + (k - 256)];
    g_B[i] = f2h(v);
}

__global__ void k_xconv(const float* __restrict__ x) {
    int i = blockIdx.x * blockDim.x + threadIdx.x;
    if (i >= NN * HD) return;
    g_X0[i] = f2h(x[i]);
}

// ---------------- agg body (one warp per node, edge loop unrolled x4) ----------------
__device__ __forceinline__ void acc8(float* acc, uint4 v) {
    float2 p;
    p = __half22float2(*(const __half2*)&v.x); acc[0] += p.x; acc[1] += p.y;
    p = __half22float2(*(const __half2*)((const char*)&v.x + 4)); acc[2] += p.x; acc[3] += p.y;
    p = __half22float2(*(const __half2*)&v.z); acc[4] += p.x; acc[5] += p.y;
    p = __half22float2(*(const __half2*)((const char*)&v.z + 4)); acc[6] += p.x; acc[7] += p.y;
}

__device__ __forceinline__ void agg_body(int aggIdx, const unsigned short* __restrict__ in) {
    int node = aggIdx * 8 + (threadIdx.x >> 5);
    int lane = threadIdx.x & 31;
    if (node >= NN) return;
    int s = g_rowptr[node], e = g_rowptr[node + 1];
    float acc[8];
#pragma unroll
    for (int j = 0; j < 8; ++j) acc[j] = 0.f;
    int i = s;
    for (; i + 4 <= e; i += 4) {
        int c0 = g_col[i], c1 = g_col[i + 1], c2 = g_col[i + 2], c3 = g_col[i + 3];
        uint4 v0 = *(const uint4*)(in + (size_t)c0 * HD + lane * 8);
        uint4 v1 = *(const uint4*)(in + (size_t)c1 * HD + lane * 8);
        uint4 v2 = *(const uint4*)(in + (size_t)c2 * HD + lane * 8);
        uint4 v3 = *(const uint4*)(in + (size_t)c3 * HD + lane * 8);
        acc8(acc, v0); acc8(acc, v1); acc8(acc, v2); acc8(acc, v3);
    }
    for (; i < e; ++i) {
        uint4 v = *(const uint4*)(in + (size_t)g_col[i] * HD + lane * 8);
        acc8(acc, v);
    }
    float sc = g_invdeg[node];
    uint32_t w[4];
#pragma unroll
    for (int p2 = 0; p2 < 4; ++p2) {
        __half2 h = __floats2half2_rn(acc[2 * p2] * sc, acc[2 * p2 + 1] * sc);
        w[p2] = *(uint32_t*)&h;
    }
    *(uint4*)(g_AG + (size_t)node * HD + lane * 8) = make_uint4(w[0], w[1], w[2], w[3]);
}

// ---------------- gemm-X body: partial = Xin * Wr -> g_P (fp32) ----------------
__device__ __forceinline__ void gemmx_body(int gidx, int layer,
                                           const unsigned short* __restrict__ Xin,
                                           char* smem) {
    const uint32_t sbase = smem_u32(smem);
    const int tid = threadIdx.x;
    const int bm = (gidx >> 1) * 128;
    const int bn = (gidx & 1) * 128;
    const int wid = tid >> 5, lane = tid & 31;
    const int wm = (wid & 1) * 64;
    const int wn = (wid >> 1) * 32;
    const unsigned short* BL = g_B + (size_t)layer * 256 * 512;

    float acc[4][4][4];
#pragma unroll
    for (int a = 0; a < 4; ++a)
#pragma unroll
        for (int b = 0; b < 4; ++b)
#pragma unroll
            for (int c = 0; c < 4; ++c) acc[a][b][c] = 0.f;

    const int frow = tid >> 1;
    const int fpart = tid & 1;

#define FILLX(cc) do {                                                          \
        int _c = (cc);                                                          \
        const unsigned short* _Asrc = Xin + (size_t)(bm + frow) * HD + _c * 64; \
        const unsigned short* _Bs = BL + (size_t)(bn + frow) * 512 + 256 + _c * 64; \
        uint32_t _sA = sbase + (_c & 1) * STAGE_BYTES;                          \
        _Pragma("unroll")                                                       \
        for (int _j = 0; _j < 4; ++_j) {                                        \
            int _c16 = fpart * 4 + _j;                                          \
            uint32_t _so = SW128(frow * 128 + _c16 * 16);                       \
            CP16(_sA + _so,         (const char*)_Asrc + _c16 * 16);            \
            CP16(_sA + 16384 + _so, (const char*)_Bs + _c16 * 16);              \
        }                                                                       \
        CP_COMMIT();                                                            \
    } while (0)

    const int arow = wm + (lane & 15);
    const int akoff = (lane >> 4) * 8;
    const int brow = wn + (lane & 7) + ((lane >> 4) << 3);
    const int bkoff = ((lane >> 3) & 1) * 8;

    FILLX(0);
    for (int c = 0; c < 4; ++c) {
        if (c + 1 < 4) FILLX(c + 1);
        else CP_COMMIT();
        CP_WAIT(1);
        __syncthreads();
        const uint32_t sA = sbase + (c & 1) * STAGE_BYTES;
        const uint32_t sB = sA + 16384;
#pragma unroll
        for (int k16 = 0; k16 < 4; ++k16) {
            uint32_t afr[4][4], bfr[2][4];
#pragma unroll
            for (int mi = 0; mi < 4; ++mi)
                ldsm4(afr[mi], sA + SW128((arow + mi * 16) * 128 + (k16 * 16 + akoff) * 2));
#pragma unroll
            for (int nt = 0; nt < 2; ++nt)
                ldsm4(bfr[nt], sB + SW128((brow + nt * 16) * 128 + (k16 * 16 + bkoff) * 2));
#pragma unroll
            for (int mi = 0; mi < 4; ++mi)
#pragma unroll
                for (int ni = 0; ni < 4; ++ni)
                    mma16816(acc[mi][ni], afr[mi], &bfr[ni >> 1][(ni & 1) * 2]);
        }
        __syncthreads();
    }
#undef FILLX

    // store raw fp32 partial
    const int r0 = lane >> 2;
    const int c01 = (lane & 3) * 2;
#pragma unroll
    for (int mi = 0; mi < 4; ++mi)
#pragma unroll
        for (int half = 0; half < 2; ++half) {
            int m = bm + wm + mi * 16 + r0 + half * 8;
#pragma unroll
            for (int ni = 0; ni < 4; ++ni) {
                int gn = bn + wn + ni * 8 + c01;
                *(float2*)(g_P + (size_t)m * HD + gn) =
                    make_float2(acc[mi][ni][half * 2 + 0], acc[mi][ni][half * 2 + 1]);
            }
        }
}

// ---------------- k1: interleaved agg + gemm-X (1:8 by blockIdx) ----------------
__global__ __launch_bounds__(256, 2)
void k_agg_gemmx(int layer, const unsigned short* __restrict__ Xin) {
    extern __shared__ char smem[];
    int bid = blockIdx.x;
    int g = bid / 9;
    if (bid % 9 == 0) {
        gemmx_body(g, layer, Xin, smem);
    } else {
        agg_body(bid - g - 1, Xin);
    }
}

// ---------------- k2: out = ELU(AG*Wl + partial + bias) ----------------
__global__ __launch_bounds__(256, 2)
void k_gemm_ag(int layer, const float* __restrict__ bias,
               float* __restrict__ outp, int final_layer,
               unsigned short* __restrict__ Xout) {
    extern __shared__ char smem[];
    const uint32_t sbase = smem_u32(smem);
    const int tid = threadIdx.x;
    const int bm = blockIdx.x * 128;
    const int bn = blockIdx.y * 128;
    const int wid = tid >> 5, lane = tid & 31;
    const int wm = (wid & 1) * 64;
    const int wn = (wid >> 1) * 32;
    const unsigned short* BL = g_B + (size_t)layer * 256 * 512;

    float acc[4][4][4];
#pragma unroll
    for (int a = 0; a < 4; ++a)
#pragma unroll
        for (int b = 0; b < 4; ++b)
#pragma unroll
            for (int c = 0; c < 4; ++c) acc[a][b][c] = 0.f;

    const int frow = tid >> 1;
    const int fpart = tid & 1;

#define FILLA(cc) do {                                                          \
        int _c = (cc);                                                          \
        const unsigned short* _Asrc = g_AG + (size_t)(bm + frow) * HD + _c * 64;\
        const unsigned short* _Bs = BL + (size_t)(bn + frow) * 512 + _c * 64;   \
        uint32_t _sA = sbase + (_c & 1) * STAGE_BYTES;                          \
        _Pragma("unroll")                                                       \
        for (int _j = 0; _j < 4; ++_j) {                                        \
            int _c16 = fpart * 4 + _j;                                          \
            uint32_t _so = SW128(frow * 128 + _c16 * 16);                       \
            CP16(_sA + _so,         (const char*)_Asrc + _c16 * 16);            \
            CP16(_sA + 16384 + _so, (const char*)_Bs + _c16 * 16);              \
        }                                                                       \
        CP_COMMIT();                                                            \
    } while (0)

    const int arow = wm + (lane & 15);
    const int akoff = (lane >> 4) * 8;
    const int brow = wn + (lane & 7) + ((lane >> 4) << 3);
    const int bkoff = ((lane >> 3) & 1) * 8;

    FILLA(0);
    for (int c = 0; c < 4; ++c) {
        if (c + 1 < 4) FILLA(c + 1);
        else CP_COMMIT();
        CP_WAIT(1);
        __syncthreads();
        const uint32_t sA = sbase + (c & 1) * STAGE_BYTES;
        const uint32_t sB = sA + 16384;
#pragma unroll
        for (int k16 = 0; k16 < 4; ++k16) {
            uint32_t afr[4][4], bfr[2][4];
#pragma unroll
            for (int mi = 0; mi < 4; ++mi)
                ldsm4(afr[mi], sA + SW128((arow + mi * 16) * 128 + (k16 * 16 + akoff) * 2));
#pragma unroll
            for (int nt = 0; nt < 2; ++nt)
                ldsm4(bfr[nt], sB + SW128((brow + nt * 16) * 128 + (k16 * 16 + bkoff) * 2));
#pragma unroll
            for (int mi = 0; mi < 4; ++mi)
#pragma unroll
                for (int ni = 0; ni < 4; ++ni)
                    mma16816(acc[mi][ni], afr[mi], &bfr[ni >> 1][(ni & 1) * 2]);
        }
        __syncthreads();
    }
#undef FILLA

    // epilogue: + partial + bias, ELU, store
    const int r0 = lane >> 2;
    const int c01 = (lane & 3) * 2;
#pragma unroll
    for (int mi = 0; mi < 4; ++mi) {
#pragma unroll
        for (int half = 0; half < 2; ++half) {
            int m = bm + wm + mi * 16 + r0 + half * 8;
            if (m >= NN) continue;
#pragma unroll
            for (int ni = 0; ni < 4; ++ni) {
                int gn = bn + wn + ni * 8 + c01;
                float2 pp = *(const float2*)(g_P + (size_t)m * HD + gn);
                float v0 = acc[mi][ni][half * 2 + 0] + pp.x + bias[gn];
                float v1 = acc[mi][ni][half * 2 + 1] + pp.y + bias[gn + 1];
                v0 = (v0 > 0.f) ? v0 : expm1f(v0);
                v1 = (v1 > 0.f) ? v1 : expm1f(v1);
                if (final_layer) {
                    *(float2*)(outp + (size_t)m * HD + gn) = make_float2(v0, v1);
                } else {
                    __half2 hv = __floats2half2_rn(v0, v1);
                    *(uint32_t*)(Xout + (size_t)m * HD + gn) = *(uint32_t*)&hv;
                }
            }
        }
    }
}

// ---------------- launch ----------------
extern "C" void kernel_launch(void* const* d_in, const int* in_sizes, int n_in,
                              void* d_out, int out_size)
{
    const float* x = nullptr;
    const int* edge32 = nullptr;
    const float* W[6] = {};
    const float* B[3] = {};
    int wi = 0, bi = 0;
    for (int i = 0; i < n_in; ++i) {
        int s = in_sizes[i];
        if (s == NN * HD)            x = (const float*)d_in[i];
        else if (s == 2 * NE)        edge32 = (const int*)d_in[i];
        else if (s == HD * HD) { if (wi < 6) W[wi++] = (const float*)d_in[i]; }
        else if (s == HD)      { if (bi < 3) B[bi++] = (const float*)d_in[i]; }
    }
    float* out = (float*)d_out;

    unsigned short *x0, *x1;
    cudaGetSymbolAddress((void**)&x0, g_X0);
    cudaGetSymbolAddress((void**)&x1, g_X1);

    cudaFuncSetAttribute(k_agg_gemmx, cudaFuncAttributeMaxDynamicSharedMemorySize, SMEM_TOTAL);
    cudaFuncSetAttribute(k_gemm_ag, cudaFuncAttributeMaxDynamicSharedMemorySize, SMEM_TOTAL);

    // edge dtype probe + normalize to int32 src/dst (+ degree count fused)
    k_zero_detect<<<(NN + 255) / 256, 256>>>(edge32);
    k_detect<<<(4096 + 255) / 256, 256>>>(edge32);
    k_convert_count<<<(NE + 255) / 256, 256>>>(edge32);

    // CSR build: parallel 3-phase scan + fill
    k_blocksum<<<NBLK, 256>>>();
    k_scanpart<<<1, 256>>>();
    k_rowptr<<<NBLK, 256>>>();
    k_fill<<<(NE + 255) / 256, 256>>>();

    // weight + input conversion to fp16
    k_wconv<<<(3 * 256 * 512 + 255) / 256, 256>>>(W[0], W[1], W[2], W[3], W[4], W[5]);
    k_xconv<<<(NN * HD + 255) / 256, 256>>>(x);

    dim3 ggrid(MPAD / 128, 2);              // 391 x 2

    // layer 1: X0 -> X1
    k_agg_gemmx<<<K1_GRID, 256, SMEM_TOTAL>>>(0, x0);
    k_gemm_ag<<<ggrid, 256, SMEM_TOTAL>>>(0, B[0], out, 0, x1);
    // layer 2: X1 -> X0
    k_agg_gemmx<<<K1_GRID, 256, SMEM_TOTAL>>>(1, x1);
    k_gemm_ag<<<ggrid, 256, SMEM_TOTAL>>>(1, B[1], out, 0, x0);
    // layer 3: X0 -> out
    k_agg_gemmx<<<K1_GRID, 256, SMEM_TOTAL>>>(2, x0);
    k_gemm_ag<<<ggrid, 256, SMEM_TOTAL>>>(2, B[2], out, 1, x1);
}